// round 2
// baseline (speedup 1.0000x reference)
#include <cuda_runtime.h>
#include <cstring>

#define HH 256
#define WW 512
#define CIN 32
#define COUT 64
#define KK 9
#define BB 2
#define HWSZ (HH * WW)           /* 131072 */
#define NPIX (BB * HWSZ)         /* 262144 */
#define CK (CIN * KK)            /* 288 */
#define TP 64                    /* pixels per tile */
#define NTILES (NPIX / TP)       /* 4096 */
#define THREADS 512
#define S_STRIDE 132             /* floats per Ssh row: 2*TP + 4 pad (16B-aligned rows) */
#define OS (TP + 2)              /* epilogue stage stride */

// Scratch: transposed input  xt[b][h][w][c]  (33.5 MB)
__device__ float g_xt[(size_t)NPIX * CIN];

// packed f32x2 FMA: acc += a * b (elementwise on two fp32 lanes)
#define FMA2(acc, a, b) \
    asm("fma.rn.f32x2 %0, %1, %2, %0;" : "+l"(acc) : "l"(a), "l"(b))

// ---------------------------------------------------------------------------
// Kernel 1: transpose [B, C, H, W] -> [B, H*W, C]
// ---------------------------------------------------------------------------
__global__ void transpose_kernel(const float* __restrict__ x) {
    __shared__ float tile[32][33];
    const int b  = blockIdx.y;
    const int s0 = blockIdx.x * 32;          // spatial base
    const int tx = threadIdx.x;              // 0..31
    const int ty = threadIdx.y;              // 0..7
    const float* xb = x + (size_t)b * CIN * HWSZ;
#pragma unroll
    for (int i = 0; i < 4; i++) {
        const int c = ty + i * 8;
        tile[c][tx] = __ldg(&xb[(size_t)c * HWSZ + s0 + tx]);
    }
    __syncthreads();
    float* xtb = g_xt + ((size_t)b * HWSZ + s0) * CIN;
#pragma unroll
    for (int i = 0; i < 4; i++) {
        const int srow = ty + i * 8;         // spatial within tile
        xtb[srow * CIN + tx] = tile[tx][srow];
    }
}

// ---------------------------------------------------------------------------
// Kernel 2: fused gather + implicit GEMM
//   smem: Wsh[CK][COUT]               73728 B
//         Ssh[CK][S_STRIDE] (dup'd)  152064 B   total 225792 B
// ---------------------------------------------------------------------------
extern __shared__ float smem_dyn[];

__global__ void __launch_bounds__(THREADS, 1) mapped_conv_kernel(
    const float* __restrict__ smap,     // [OH*OW, K, 2]
    const float* __restrict__ weight,   // [COUT, CIN, K]
    const float* __restrict__ bias,     // [COUT]
    float* __restrict__ out)            // [B, COUT, OH*OW]
{
    float* Wsh = smem_dyn;               // [CK][COUT]
    float* Ssh = smem_dyn + CK * COUT;   // [CK][S_STRIDE]

    const int tid  = threadIdx.x;
    const int warp = tid >> 5;
    const int lane = tid & 31;

    // Load weights: coalesced gmem read, scatter to Wsh[k*CIN+c][o]
    for (int idx = tid; idx < COUT * CK; idx += THREADS) {
        const int o = idx / CK;
        const int r = idx - o * CK;       // c*KK + k
        const int c = r / KK;
        const int k = r - c * KK;
        Wsh[(k * CIN + c) * COUT + o] = weight[idx];
    }
    __syncthreads();

    for (int t = blockIdx.x; t < NTILES; t += gridDim.x) {
        const int gp0 = t * TP;

        // ---------------- gather phase: warp per (pixel,k), lane per channel
#pragma unroll 2
        for (int idx = warp; idx < TP * KK; idx += (THREADS / 32)) {
            const int p  = idx / KK;
            const int k  = idx - p * KK;
            const int gp = gp0 + p;
            const int b  = gp >> 17;            // / HWSZ
            const int s  = gp & (HWSZ - 1);

            const float sx = __ldg(&smap[(s * KK + k) * 2 + 0]);
            const float sy = __ldg(&smap[(s * KK + k) * 2 + 1]);
            const float bx = floorf(sx), by = floorf(sy);
            const float fx = sx - bx,  fy = sy - by;
            const int x0 = (int)bx,    y0 = (int)by;
            const int x0c = min(max(x0,     0), WW - 1);
            const int x1c = min(max(x0 + 1, 0), WW - 1);
            const int y0c = min(max(y0,     0), HH - 1);
            const int y1c = min(max(y0 + 1, 0), HH - 1);

            const float* base = g_xt + (size_t)b * HWSZ * CIN;
            const float v00 = __ldg(&base[(y0c * WW + x0c) * CIN + lane]);
            const float v01 = __ldg(&base[(y0c * WW + x1c) * CIN + lane]);
            const float v10 = __ldg(&base[(y1c * WW + x0c) * CIN + lane]);
            const float v11 = __ldg(&base[(y1c * WW + x1c) * CIN + lane]);

            const float gx = 1.0f - fx;
            const float top = v00 * gx + v01 * fx;
            const float bot = v10 * gx + v11 * fx;
            const float v   = top * (1.0f - fy) + bot * fy;

            // duplicated store (v, v) for packed-FMA consumption
            float2 vv = make_float2(v, v);
            *reinterpret_cast<float2*>(&Ssh[(k * CIN + lane) * S_STRIDE + 2 * p]) = vv;
        }
        __syncthreads();

        // ---------------- GEMM phase: thread = (o,o+1) pair x 4 pixels
        const int p0 = warp * 4;            // pixel base (warp-uniform)
        const int oo = lane * 2;            // output-channel pair

        unsigned long long a0 = 0ull, a1 = 0ull, a2 = 0ull, a3 = 0ull;
        const float* wrow = Wsh + oo;
        const float* srow = Ssh + 2 * p0;
#pragma unroll 4
        for (int ck = 0; ck < CK; ck++) {
            const unsigned long long w2 =
                *reinterpret_cast<const unsigned long long*>(wrow + ck * COUT);
            const ulonglong2 sA =
                *reinterpret_cast<const ulonglong2*>(srow + ck * S_STRIDE);
            const ulonglong2 sB =
                *reinterpret_cast<const ulonglong2*>(srow + ck * S_STRIDE + 4);
            FMA2(a0, w2, sA.x);
            FMA2(a1, w2, sA.y);
            FMA2(a2, w2, sB.x);
            FMA2(a3, w2, sB.y);
        }
        __syncthreads();   // Ssh reuse below

        // ---------------- epilogue: stage to smem, coalesced store + bias
        float* Osh = Ssh;  // [COUT][OS]
        {
            const unsigned long long av[4] = {a0, a1, a2, a3};
#pragma unroll
            for (int j = 0; j < 4; j++) {
                const float lo = __uint_as_float((unsigned)(av[j] & 0xffffffffu));
                const float hi = __uint_as_float((unsigned)(av[j] >> 32));
                Osh[oo * OS + p0 + j]       = lo;
                Osh[(oo + 1) * OS + p0 + j] = hi;
            }
        }
        __syncthreads();

        const int b  = gp0 >> 17;
        const int s  = gp0 & (HWSZ - 1);
#pragma unroll
        for (int idx = tid; idx < COUT * TP; idx += THREADS) {
            const int o = idx >> 6;    // / TP
            const int p = idx & (TP - 1);
            out[((size_t)(b * COUT + o)) * HWSZ + s + p] =
                Osh[o * OS + p] + __ldg(&bias[o]);
        }
        __syncthreads();   // protect Osh/Ssh before next tile's gather
    }
}

// ---------------------------------------------------------------------------
// launch
// ---------------------------------------------------------------------------
extern "C" void kernel_launch(void* const* d_in, const int* in_sizes, int n_in,
                              void* d_out, int out_size) {
    // Identify inputs by element count (all distinct):
    //   x: 8388608, weight: 18432, bias: 64, sample_map: 2359296
    const float* x = nullptr;
    const float* weight = nullptr;
    const float* bias = nullptr;
    const float* smap = nullptr;
    for (int i = 0; i < n_in; i++) {
        switch (in_sizes[i]) {
            case 8388608: x      = (const float*)d_in[i]; break;
            case 18432:   weight = (const float*)d_in[i]; break;
            case 64:      bias   = (const float*)d_in[i]; break;
            case 2359296: smap   = (const float*)d_in[i]; break;
            default: break;
        }
    }
    float* out = (float*)d_out;

    static bool attr_set = false;
    const int smem_bytes = (CK * COUT + CK * S_STRIDE) * 4;  // 225792
    if (!attr_set) {
        cudaFuncSetAttribute(mapped_conv_kernel,
                             cudaFuncAttributeMaxDynamicSharedMemorySize,
                             smem_bytes);
        attr_set = true;
    }

    // 1) transpose x -> g_xt
    {
        dim3 grid(HWSZ / 32, BB);
        dim3 block(32, 8);
        transpose_kernel<<<grid, block>>>(x);
    }

    // 2) fused gather + GEMM (persistent-ish CTAs, 1 CTA/SM due to smem)
    mapped_conv_kernel<<<304, THREADS, smem_bytes>>>(smap, weight, bias, out);
}

// round 4
// speedup vs baseline: 1.2679x; 1.2679x over previous
#include <cuda_runtime.h>
#include <cstring>

#define HH 256
#define WW 512
#define CIN 32
#define COUT 64
#define KK 9
#define BB 2
#define HWSZ (HH * WW)           /* 131072 */
#define NPIX (BB * HWSZ)         /* 262144 */
#define CK (CIN * KK)            /* 288 */
#define TP 64                    /* pixels per tile */
#define NTILES (NPIX / TP)       /* 4096 */
#define THREADS 512
#define S_STRIDE 132             /* floats/row: 528 B = 16B-aligned (LDS.128 ok); STS.64 2-way conflict only */
#define OS 65                    /* epilogue stage stride (pixel-major), odd -> conflict-free reads */

// Scratch: transposed input  xt[b][h][w][c]  (33.5 MB)
__device__ float g_xt[(size_t)NPIX * CIN];

// packed f32x2 FMA: acc += a * b (elementwise on two fp32 lanes)
#define FMA2(acc, a, b) \
    asm("fma.rn.f32x2 %0, %1, %2, %0;" : "+l"(acc) : "l"(a), "l"(b))

// ---------------------------------------------------------------------------
// Kernel 1: transpose [B, C, H, W] -> [B, H*W, C]
// ---------------------------------------------------------------------------
__global__ void transpose_kernel(const float* __restrict__ x) {
    __shared__ float tile[32][33];
    const int b  = blockIdx.y;
    const int s0 = blockIdx.x * 32;          // spatial base
    const int tx = threadIdx.x;              // 0..31
    const int ty = threadIdx.y;              // 0..7
    const float* xb = x + (size_t)b * CIN * HWSZ;
#pragma unroll
    for (int i = 0; i < 4; i++) {
        const int c = ty + i * 8;
        tile[c][tx] = __ldg(&xb[(size_t)c * HWSZ + s0 + tx]);
    }
    __syncthreads();
    float* xtb = g_xt + ((size_t)b * HWSZ + s0) * CIN;
#pragma unroll
    for (int i = 0; i < 4; i++) {
        const int srow = ty + i * 8;         // spatial within tile
        xtb[srow * CIN + tx] = tile[tx][srow];
    }
}

// ---------------------------------------------------------------------------
// Kernel 2: fused gather + implicit GEMM
//   smem: Wsh[CK][COUT]               73728 B
//         Bsh[COUT]                     256 B
//         Ssh[CK][S_STRIDE] (dup'd)  152064 B   total 226048 B
// ---------------------------------------------------------------------------
extern __shared__ float smem_dyn[];

__global__ void __launch_bounds__(THREADS, 1) mapped_conv_kernel(
    const float* __restrict__ smap,     // [OH*OW, K, 2]
    const float* __restrict__ weight,   // [COUT, CIN, K]
    const float* __restrict__ bias,     // [COUT]
    float* __restrict__ out)            // [B, COUT, OH*OW]
{
    float* Wsh = smem_dyn;                       // [CK][COUT]
    float* Bsh = smem_dyn + CK * COUT;           // [COUT]
    float* Ssh = smem_dyn + CK * COUT + COUT;    // [CK][S_STRIDE]

    const int tid  = threadIdx.x;
    const int warp = tid >> 5;
    const int lane = tid & 31;

    // Load weights: coalesced gmem read, scatter to Wsh[k*CIN+c][o]
    for (int idx = tid; idx < COUT * CK; idx += THREADS) {
        const int o = idx / CK;
        const int r = idx - o * CK;       // c*KK + k
        const int c = r / KK;
        const int k = r - c * KK;
        Wsh[(k * CIN + c) * COUT + o] = weight[idx];
    }
    if (tid < COUT) Bsh[tid] = bias[tid];
    __syncthreads();

    for (int t = blockIdx.x; t < NTILES; t += gridDim.x) {
        const int gp0 = t * TP;
        const int b   = gp0 >> 17;           // / HWSZ (whole tile is one batch)
        const int s0  = gp0 & (HWSZ - 1);
        const float* __restrict__ xbase = g_xt + (size_t)b * HWSZ * CIN;

        // ---------------- gather phase: warp per (pixel,k), lane per channel
#pragma unroll 4
        for (int idx = warp; idx < TP * KK; idx += (THREADS / 32)) {
            const int p  = idx / KK;
            const int k  = idx - p * KK;
            const int s  = s0 + p;

            const float2 sxy = __ldg(reinterpret_cast<const float2*>(
                                         smap + (s * KK + k) * 2));
            const float bx = floorf(sxy.x), by = floorf(sxy.y);
            const float fx = sxy.x - bx,  fy = sxy.y - by;
            const int x0 = (int)bx,    y0 = (int)by;
            const int x0c = min(max(x0,     0), WW - 1);
            const int x1c = min(max(x0 + 1, 0), WW - 1);
            const int y0c = min(max(y0,     0), HH - 1);
            const int y1c = min(max(y0 + 1, 0), HH - 1);

            const float v00 = __ldg(&xbase[(y0c * WW + x0c) * CIN + lane]);
            const float v01 = __ldg(&xbase[(y0c * WW + x1c) * CIN + lane]);
            const float v10 = __ldg(&xbase[(y1c * WW + x0c) * CIN + lane]);
            const float v11 = __ldg(&xbase[(y1c * WW + x1c) * CIN + lane]);

            const float gx = 1.0f - fx;
            const float top = v00 * gx + v01 * fx;
            const float bot = v10 * gx + v11 * fx;
            const float v   = top * (1.0f - fy) + bot * fy;

            // duplicated store (v, v) for packed-FMA consumption
            float2 vv = make_float2(v, v);
            *reinterpret_cast<float2*>(&Ssh[(k * CIN + lane) * S_STRIDE + 2 * p]) = vv;
        }
        __syncthreads();

        // ---------------- GEMM phase: thread = (o,o+1) pair x 4 pixels
        const int p0 = warp * 4;            // pixel base (warp-uniform)
        const int oo = lane * 2;            // output-channel pair

        unsigned long long a0 = 0ull, a1 = 0ull, a2 = 0ull, a3 = 0ull;
        const float* wrow = Wsh + oo;
        const float* srow = Ssh + 2 * p0;
#pragma unroll 4
        for (int ck = 0; ck < CK; ck++) {
            const unsigned long long w2 =
                *reinterpret_cast<const unsigned long long*>(wrow + ck * COUT);
            const ulonglong2 sA =
                *reinterpret_cast<const ulonglong2*>(srow + ck * S_STRIDE);
            const ulonglong2 sB =
                *reinterpret_cast<const ulonglong2*>(srow + ck * S_STRIDE + 4);
            FMA2(a0, w2, sA.x);
            FMA2(a1, w2, sA.y);
            FMA2(a2, w2, sB.x);
            FMA2(a3, w2, sB.y);
        }
        __syncthreads();   // Ssh reuse below

        // ---------------- epilogue: stage pixel-major, coalesced store + bias
        float* Osh = Ssh;  // [TP][OS]
        {
            const unsigned long long av[4] = {a0, a1, a2, a3};
#pragma unroll
            for (int j = 0; j < 4; j++) {
                const float lo = __uint_as_float((unsigned)(av[j] & 0xffffffffu));
                const float hi = __uint_as_float((unsigned)(av[j] >> 32));
                // lane-stride = 2 floats -> 2-way conflict max
                Osh[(p0 + j) * OS + oo]     = lo;
                Osh[(p0 + j) * OS + oo + 1] = hi;
            }
        }
        __syncthreads();

#pragma unroll
        for (int idx = tid; idx < COUT * TP; idx += THREADS) {
            const int o = idx >> 6;    // / TP
            const int p = idx & (TP - 1);
            // read stride OS=65 (odd) -> conflict-free; gmem write coalesced
            out[((size_t)(b * COUT + o)) * HWSZ + s0 + p] =
                Osh[p * OS + o] + Bsh[o];
        }
        __syncthreads();   // protect Osh/Ssh before next tile's gather
    }
}

// ---------------------------------------------------------------------------
// launch
// ---------------------------------------------------------------------------
extern "C" void kernel_launch(void* const* d_in, const int* in_sizes, int n_in,
                              void* d_out, int out_size) {
    // Identify inputs by element count (all distinct):
    //   x: 8388608, weight: 18432, bias: 64, sample_map: 2359296
    const float* x = nullptr;
    const float* weight = nullptr;
    const float* bias = nullptr;
    const float* smap = nullptr;
    for (int i = 0; i < n_in; i++) {
        switch (in_sizes[i]) {
            case 8388608: x      = (const float*)d_in[i]; break;
            case 18432:   weight = (const float*)d_in[i]; break;
            case 64:      bias   = (const float*)d_in[i]; break;
            case 2359296: smap   = (const float*)d_in[i]; break;
            default: break;
        }
    }
    float* out = (float*)d_out;

    const int smem_bytes = (CK * COUT + COUT + CK * S_STRIDE) * 4;  // 226048

    static int n_sm = 0;
    if (n_sm == 0) {
        cudaFuncSetAttribute(mapped_conv_kernel,
                             cudaFuncAttributeMaxDynamicSharedMemorySize,
                             smem_bytes);
        cudaDeviceGetAttribute(&n_sm, cudaDevAttrMultiProcessorCount, 0);
        if (n_sm <= 0) n_sm = 148;
    }

    // 1) transpose x -> g_xt
    {
        dim3 grid(HWSZ / 32, BB);
        dim3 block(32, 8);
        transpose_kernel<<<grid, block>>>(x);
    }

    // 2) fused gather + GEMM: persistent CTAs, exactly one wave (1 CTA/SM)
    mapped_conv_kernel<<<n_sm, THREADS, smem_bytes>>>(smap, weight, bias, out);
}

// round 7
// speedup vs baseline: 1.4547x; 1.1473x over previous
#include <cuda_runtime.h>
#include <cstring>

#define HH 256
#define WW 512
#define CIN 32
#define COUT 64
#define KK 9
#define BB 2
#define HWSZ (HH * WW)           /* 131072 */
#define NPIX (BB * HWSZ)         /* 262144 */
#define CK (CIN * KK)            /* 288 */
#define TP 64                    /* pixels per tile */
#define NTILES (NPIX / TP)       /* 4096 */
#define THREADS 512
#define NWARP (THREADS / 32)
#define S_STRIDE 132             /* floats/row: 528 B, 16B-aligned rows for LDS.128 */

// Scratch: transposed input  xt[b][h][w][c]  (33.5 MB)
__device__ float g_xt[(size_t)NPIX * CIN];

// packed f32x2 FMA: acc += a * b (elementwise on two fp32 lanes)
#define FMA2(acc, a, b) \
    asm("fma.rn.f32x2 %0, %1, %2, %0;" : "+l"(acc) : "l"(a), "l"(b))

// ---------------------------------------------------------------------------
// Kernel 1: transpose [B, C, H, W] -> [B, H*W, C]
// ---------------------------------------------------------------------------
__global__ void transpose_kernel(const float* __restrict__ x) {
    __shared__ float tile[32][33];
    const int b  = blockIdx.y;
    const int s0 = blockIdx.x * 32;          // spatial base
    const int tx = threadIdx.x;              // 0..31
    const int ty = threadIdx.y;              // 0..7
    const float* xb = x + (size_t)b * CIN * HWSZ;
#pragma unroll
    for (int i = 0; i < 4; i++) {
        const int c = ty + i * 8;
        tile[c][tx] = __ldg(&xb[(size_t)c * HWSZ + s0 + tx]);
    }
    __syncthreads();
    float* xtb = g_xt + ((size_t)b * HWSZ + s0) * CIN;
#pragma unroll
    for (int i = 0; i < 4; i++) {
        const int srow = ty + i * 8;         // spatial within tile
        xtb[srow * CIN + tx] = tile[tx][srow];
    }
}

// ---------------------------------------------------------------------------
// Kernel 2: fused gather + implicit GEMM
//   smem: Wsh[CK][COUT]               73728 B
//         Ssh[CK][S_STRIDE] (dup'd)  152064 B   total 225792 B
// ---------------------------------------------------------------------------
extern __shared__ float smem_dyn[];

__global__ void __launch_bounds__(THREADS, 1) mapped_conv_kernel(
    const float* __restrict__ smap,     // [OH*OW, K, 2]
    const float* __restrict__ weight,   // [COUT, CIN, K]
    const float* __restrict__ bias,     // [COUT]
    float* __restrict__ out)            // [B, COUT, OH*OW]
{
    float* Wsh = smem_dyn;               // [CK][COUT]
    float* Ssh = smem_dyn + CK * COUT;   // [CK][S_STRIDE]

    const int tid  = threadIdx.x;
    const int warp = tid >> 5;
    const int lane = tid & 31;

    // Load weights: coalesced gmem read, scatter to Wsh[k*CIN+c][o]
    for (int idx = tid; idx < COUT * CK; idx += THREADS) {
        const int o = idx / CK;
        const int r = idx - o * CK;       // c*KK + k
        const int c = r / KK;
        const int k = r - c * KK;
        Wsh[(k * CIN + c) * COUT + o] = weight[idx];
    }

    // Per-thread output-channel pair + bias in registers (hoisted for epilogue)
    const int oo   = lane * 2;
    const float b_lo = __ldg(&bias[oo]);
    const float b_hi = __ldg(&bias[oo + 1]);
    __syncthreads();

    for (int t = blockIdx.x; t < NTILES; t += gridDim.x) {
        const int gp0 = t * TP;
        const int b   = gp0 >> 17;           // / HWSZ (whole tile is one batch)
        const int s0  = gp0 & (HWSZ - 1);
        const float* __restrict__ xbase = g_xt + (size_t)b * HWSZ * CIN + lane;

        // ---------------- gather phase: warp per pixel, lane per channel,
        //                  k fully unrolled (9 smap + 36 corner LDGs batched)
#pragma unroll 1
        for (int pp = warp; pp < TP; pp += NWARP) {
            const int s = s0 + pp;
            const float2* __restrict__ smp =
                reinterpret_cast<const float2*>(smap) + s * KK;
            float* __restrict__ sdst = Ssh + lane * S_STRIDE + 2 * pp;

#pragma unroll
            for (int k = 0; k < KK; k++) {
                const float2 sxy = __ldg(&smp[k]);
                const float bx = floorf(sxy.x), by = floorf(sxy.y);
                const float fx = sxy.x - bx,  fy = sxy.y - by;
                const int x0 = (int)bx,  y0 = (int)by;        // in-range by construction
                const int x1 = min(x0 + 1, WW - 1);
                const int y1 = min(y0 + 1, HH - 1);

                const int r0 = y0 << 14;   // y*WW*CIN
                const int r1 = y1 << 14;
                const int c0 = x0 << 5;    // x*CIN
                const int c1 = x1 << 5;

                const float v00 = __ldg(xbase + r0 + c0);
                const float v01 = __ldg(xbase + r0 + c1);
                const float v10 = __ldg(xbase + r1 + c0);
                const float v11 = __ldg(xbase + r1 + c1);

                const float top = fmaf(fx, v01 - v00, v00);
                const float bot = fmaf(fx, v11 - v10, v10);
                const float v   = fmaf(fy, bot - top, top);

                // duplicated store (v, v) for packed-FMA consumption
                *reinterpret_cast<float2*>(sdst + k * (CIN * S_STRIDE)) =
                    make_float2(v, v);
            }
        }
        __syncthreads();

        // ---------------- GEMM phase: thread = (o,o+1) pair x 4 pixels
        const int p0 = warp * 4;            // pixel base (warp-uniform)

        unsigned long long a0 = 0ull, a1 = 0ull, a2 = 0ull, a3 = 0ull;
        const float* wrow = Wsh + oo;
        const float* srow = Ssh + 2 * p0;
#pragma unroll 4
        for (int ck = 0; ck < CK; ck++) {
            const unsigned long long w2 =
                *reinterpret_cast<const unsigned long long*>(wrow + ck * COUT);
            const ulonglong2 sA =
                *reinterpret_cast<const ulonglong2*>(srow + ck * S_STRIDE);
            const ulonglong2 sB =
                *reinterpret_cast<const ulonglong2*>(srow + ck * S_STRIDE + 4);
            FMA2(a0, w2, sA.x);
            FMA2(a1, w2, sA.y);
            FMA2(a2, w2, sB.x);
            FMA2(a3, w2, sB.y);
        }

        // ---------------- epilogue: direct vectorized stores (no smem, no bar)
        {
            const float l0 = __uint_as_float((unsigned)(a0 & 0xffffffffu)) + b_lo;
            const float l1 = __uint_as_float((unsigned)(a1 & 0xffffffffu)) + b_lo;
            const float l2 = __uint_as_float((unsigned)(a2 & 0xffffffffu)) + b_lo;
            const float l3 = __uint_as_float((unsigned)(a3 & 0xffffffffu)) + b_lo;
            const float h0 = __uint_as_float((unsigned)(a0 >> 32)) + b_hi;
            const float h1 = __uint_as_float((unsigned)(a1 >> 32)) + b_hi;
            const float h2 = __uint_as_float((unsigned)(a2 >> 32)) + b_hi;
            const float h3 = __uint_as_float((unsigned)(a3 >> 32)) + b_hi;

            float* olo = out + ((size_t)(b * COUT + oo)) * HWSZ + s0 + p0;
            *reinterpret_cast<float4*>(olo)         = make_float4(l0, l1, l2, l3);
            *reinterpret_cast<float4*>(olo + HWSZ)  = make_float4(h0, h1, h2, h3);
        }
        __syncthreads();   // protect Ssh (WAR) before next tile's gather
    }
}

// ---------------------------------------------------------------------------
// launch
// ---------------------------------------------------------------------------
extern "C" void kernel_launch(void* const* d_in, const int* in_sizes, int n_in,
                              void* d_out, int out_size) {
    // Identify inputs by element count (all distinct):
    //   x: 8388608, weight: 18432, bias: 64, sample_map: 2359296
    const float* x = nullptr;
    const float* weight = nullptr;
    const float* bias = nullptr;
    const float* smap = nullptr;
    for (int i = 0; i < n_in; i++) {
        switch (in_sizes[i]) {
            case 8388608: x      = (const float*)d_in[i]; break;
            case 18432:   weight = (const float*)d_in[i]; break;
            case 64:      bias   = (const float*)d_in[i]; break;
            case 2359296: smap   = (const float*)d_in[i]; break;
            default: break;
        }
    }
    float* out = (float*)d_out;

    const int smem_bytes = (CK * COUT + CK * S_STRIDE) * 4;  // 225792

    static int n_sm = 0;
    if (n_sm == 0) {
        cudaFuncSetAttribute(mapped_conv_kernel,
                             cudaFuncAttributeMaxDynamicSharedMemorySize,
                             smem_bytes);
        cudaDeviceGetAttribute(&n_sm, cudaDevAttrMultiProcessorCount, 0);
        if (n_sm <= 0) n_sm = 148;
    }

    // 1) transpose x -> g_xt
    {
        dim3 grid(HWSZ / 32, BB);
        dim3 block(32, 8);
        transpose_kernel<<<grid, block>>>(x);
    }

    // 2) fused gather + GEMM: persistent CTAs, exactly one wave (1 CTA/SM)
    mapped_conv_kernel<<<n_sm, THREADS, smem_bytes>>>(smap, weight, bias, out);
}

// round 11
// speedup vs baseline: 3.3053x; 2.2722x over previous
#include <cuda_runtime.h>
#include <cuda_bf16.h>
#include <cstdint>

#define HH 256
#define WW 512
#define CIN 32
#define COUT 64
#define KK 9
#define BB 2
#define HWSZ (HH * WW)           /* 131072 */
#define NPIX (BB * HWSZ)         /* 262144 */
#define CK 288                   /* CIN*KK */
#define TPX 128                  /* pixels per tile = GEMM M */
#define NT (NPIX / TPX)          /* 2048 tiles */
#define THREADS 512
#define NWARP 16

#define SB  296                  /* bf16 elements per smem row (288 + 8 pad) */
#define SBB (SB * 2)             /* 592 bytes per row; 592=16*37 -> 16B aligned */

/* ---- shared memory byte map ---- */
#define A_HI 1024                          /* samples hi: 128*592 = 75776 */
#define A_LO (A_HI + TPX * SBB)
#define B_HI (A_LO + TPX * SBB)            /* weights hi: 64*592 = 37888 */
#define B_LO (B_HI + COUT * SBB)
#define SMEM_BYTES (B_LO + COUT * SBB)     /* 228352 */

// Scratch: transposed input  xt[b][h][w][c]  (33.5 MB)
__device__ float g_xt[(size_t)NPIX * CIN];

__device__ __forceinline__ uint32_t smem_u32(const void* p) {
    uint32_t a;
    asm("{ .reg .u64 t; cvta.to.shared.u64 t, %1; cvt.u32.u64 %0, t; }"
        : "=r"(a) : "l"(p));
    return a;
}

__device__ __forceinline__ void ldm4(uint32_t& r0, uint32_t& r1,
                                     uint32_t& r2, uint32_t& r3,
                                     uint32_t addr) {
    asm volatile("ldmatrix.sync.aligned.m8n8.x4.shared.b16 {%0,%1,%2,%3}, [%4];"
                 : "=r"(r0), "=r"(r1), "=r"(r2), "=r"(r3) : "r"(addr));
}

__device__ __forceinline__ void mma16816(float* d,
                                         uint32_t a0, uint32_t a1,
                                         uint32_t a2, uint32_t a3,
                                         uint32_t b0, uint32_t b1) {
    asm volatile(
        "mma.sync.aligned.m16n8k16.row.col.f32.bf16.bf16.f32 "
        "{%0,%1,%2,%3}, {%4,%5,%6,%7}, {%8,%9}, {%0,%1,%2,%3};"
        : "+f"(d[0]), "+f"(d[1]), "+f"(d[2]), "+f"(d[3])
        : "r"(a0), "r"(a1), "r"(a2), "r"(a3), "r"(b0), "r"(b1));
}

// ---------------------------------------------------------------------------
// Kernel 1: transpose [B, C, H, W] -> [B, H*W, C]
// ---------------------------------------------------------------------------
__global__ void transpose_kernel(const float* __restrict__ x) {
    __shared__ float tile[32][33];
    const int b  = blockIdx.y;
    const int s0 = blockIdx.x * 32;
    const int tx = threadIdx.x;
    const int ty = threadIdx.y;
    const float* xb = x + (size_t)b * CIN * HWSZ;
#pragma unroll
    for (int i = 0; i < 4; i++) {
        const int c = ty + i * 8;
        tile[c][tx] = __ldg(&xb[(size_t)c * HWSZ + s0 + tx]);
    }
    __syncthreads();
    float* xtb = g_xt + ((size_t)b * HWSZ + s0) * CIN;
#pragma unroll
    for (int i = 0; i < 4; i++) {
        const int srow = ty + i * 8;
        xtb[srow * CIN + tx] = tile[tx][srow];
    }
}

// ---------------------------------------------------------------------------
// Kernel 2: gather (fp32 -> bf16 hi/lo) + 3-term bf16 HMMA GEMM
// ---------------------------------------------------------------------------
extern __shared__ char smem[];

__global__ void __launch_bounds__(THREADS, 1) mapped_conv_kernel(
    const float* __restrict__ smap,     // [OH*OW, K, 2]
    const float* __restrict__ weight,   // [COUT, CIN, K]
    const float* __restrict__ bias,     // [COUT]
    float* __restrict__ out)            // [B, COUT, OH*OW]
{
    const int tid  = threadIdx.x;
    const int warp = tid >> 5;
    const int lane = tid & 31;
    const uint32_t sbase = smem_u32(smem);

    // ---- one-time: weights -> B_HI/B_LO at [o][k*32+c] bf16
    for (int idx = tid; idx < COUT * CK; idx += THREADS) {
        const int o = idx / CK;
        const int r = idx - o * CK;      // c*KK + k
        const int c = r / KK;
        const int k = r - c * KK;
        const float w = weight[idx];
        const __nv_bfloat16 hi = __float2bfloat16(w);
        const __nv_bfloat16 lo = __float2bfloat16(w - __bfloat162float(hi));
        const int off = o * SBB + (k * CIN + c) * 2;
        *reinterpret_cast<__nv_bfloat16*>(smem + B_HI + off) = hi;
        *reinterpret_cast<__nv_bfloat16*>(smem + B_LO + off) = lo;
    }

    // ---- per-thread GEMM geometry
    const int mw = warp >> 2;            // 0..3 -> pixel block m0
    const int nw = warp & 3;             // 0..3 -> output block n0
    const int m0 = mw * 32;
    const int n0 = nw * 16;
    const int qr = lane >> 2;            // 0..7
    const int qc = lane & 3;             // 0..3

    // ldmatrix lane-address row components (byte offsets, k added per step)
    const uint32_t aRow = (uint32_t)((m0 + (lane & 15)) * SBB
                                     + ((lane >> 4) << 4));
    const uint32_t bRow = (uint32_t)((n0 + (lane & 7) + ((lane >> 4) << 3)) * SBB
                                     + (((lane >> 3) & 1) << 4));

    // bias registers (output cols this thread owns)
    float bs[2][2];
#pragma unroll
    for (int nt = 0; nt < 2; nt++) {
        bs[nt][0] = __ldg(&bias[n0 + nt * 8 + qc * 2]);
        bs[nt][1] = __ldg(&bias[n0 + nt * 8 + qc * 2 + 1]);
    }

    // gather geometry: half-warp per pixel, lane -> 2 channels
    const int hl = lane & 15;            // channel pair index
    const int ph = lane >> 4;            // which pixel of the pair

    __syncthreads();

    for (int t = blockIdx.x; t < NT; t += gridDim.x) {
        const int gp0 = t * TPX;
        const int b   = gp0 >> 17;
        const int s0  = gp0 & (HWSZ - 1);
        const float2* __restrict__ xb2 =
            reinterpret_cast<const float2*>(g_xt + (size_t)b * HWSZ * CIN) + hl;

        // ---------------- gather: 4 iters x (2 pixels/warp) x 9 taps
#pragma unroll 1
        for (int i = 0; i < 4; i++) {
            const int pp = warp * 8 + i * 2 + ph;
            const int s  = s0 + pp;
            const float2* __restrict__ smp =
                reinterpret_cast<const float2*>(smap) + s * KK;
            char* arow_hi = smem + A_HI + pp * SBB + hl * 4;
            char* arow_lo = smem + A_LO + pp * SBB + hl * 4;

#pragma unroll
            for (int k = 0; k < KK; k++) {
                const float2 sxy = __ldg(&smp[k]);
                const float bx = floorf(sxy.x), by = floorf(sxy.y);
                const float fx = sxy.x - bx,  fy = sxy.y - by;
                const int x0 = (int)bx,  y0 = (int)by;
                const int x1 = min(x0 + 1, WW - 1);
                const int y1 = min(y0 + 1, HH - 1);

                // float2 indices: (y*512+x)*16 + hl (hl folded into xb2)
                const int i00 = (y0 << 13) + (x0 << 4);
                const int i01 = (y0 << 13) + (x1 << 4);
                const int i10 = (y1 << 13) + (x0 << 4);
                const int i11 = (y1 << 13) + (x1 << 4);

                const float2 v00 = __ldg(xb2 + i00);
                const float2 v01 = __ldg(xb2 + i01);
                const float2 v10 = __ldg(xb2 + i10);
                const float2 v11 = __ldg(xb2 + i11);

                float2 v;
                {
                    const float tx0 = fmaf(fx, v01.x - v00.x, v00.x);
                    const float bx0 = fmaf(fx, v11.x - v10.x, v10.x);
                    v.x = fmaf(fy, bx0 - tx0, tx0);
                    const float ty0 = fmaf(fx, v01.y - v00.y, v00.y);
                    const float by0 = fmaf(fx, v11.y - v10.y, v10.y);
                    v.y = fmaf(fy, by0 - ty0, ty0);
                }

                const __nv_bfloat162 hi2 = __float22bfloat162_rn(v);
                const float2 hif = __bfloat1622float2(hi2);
                const __nv_bfloat162 lo2 = __float22bfloat162_rn(
                    make_float2(v.x - hif.x, v.y - hif.y));

                *reinterpret_cast<__nv_bfloat162*>(arow_hi + k * 64) = hi2;
                *reinterpret_cast<__nv_bfloat162*>(arow_lo + k * 64) = lo2;
            }
        }
        __syncthreads();

        // ---------------- GEMM: 3 terms (ah*bh, al*bh, ah*bl), 18 k-steps each
        float acc[2][2][4];
#pragma unroll
        for (int a = 0; a < 2; a++)
#pragma unroll
            for (int c = 0; c < 2; c++)
#pragma unroll
                for (int r = 0; r < 4; r++) acc[a][c][r] = 0.0f;

#pragma unroll
        for (int term = 0; term < 3; term++) {
            const uint32_t aBase = sbase + ((term == 1) ? A_LO : A_HI) + aRow;
            const uint32_t bBase = sbase + ((term == 2) ? B_LO : B_HI) + bRow;
#pragma unroll
            for (int ks = 0; ks < 18; ks++) {
                const uint32_t kb = ks * 32;
                uint32_t a0, a1, a2, a3, c0, c1, c2, c3, b0, b1, b2, b3;
                ldm4(a0, a1, a2, a3, aBase + kb);
                ldm4(c0, c1, c2, c3, aBase + 16 * SBB + kb);
                ldm4(b0, b1, b2, b3, bBase + kb);
                mma16816(acc[0][0], a0, a1, a2, a3, b0, b1);
                mma16816(acc[0][1], a0, a1, a2, a3, b2, b3);
                mma16816(acc[1][0], c0, c1, c2, c3, b0, b1);
                mma16816(acc[1][1], c0, c1, c2, c3, b2, b3);
            }
        }

        // ---------------- epilogue: direct stores + bias (no staging)
        float* ob = out + (size_t)(b * COUT) * HWSZ + s0;
#pragma unroll
        for (int mt = 0; mt < 2; mt++) {
            const int pixA = m0 + mt * 16 + qr;
#pragma unroll
            for (int nt = 0; nt < 2; nt++) {
                const int o0 = n0 + nt * 8 + qc * 2;
                ob[(size_t)o0 * HWSZ + pixA]           = acc[mt][nt][0] + bs[nt][0];
                ob[(size_t)(o0 + 1) * HWSZ + pixA]     = acc[mt][nt][1] + bs[nt][1];
                ob[(size_t)o0 * HWSZ + pixA + 8]       = acc[mt][nt][2] + bs[nt][0];
                ob[(size_t)(o0 + 1) * HWSZ + pixA + 8] = acc[mt][nt][3] + bs[nt][1];
            }
        }
        __syncthreads();   // protect A buffers before next tile's gather
    }
}

// ---------------------------------------------------------------------------
// launch
// ---------------------------------------------------------------------------
extern "C" void kernel_launch(void* const* d_in, const int* in_sizes, int n_in,
                              void* d_out, int out_size) {
    const float* x = nullptr;
    const float* weight = nullptr;
    const float* bias = nullptr;
    const float* smap = nullptr;
    for (int i = 0; i < n_in; i++) {
        switch (in_sizes[i]) {
            case 8388608: x      = (const float*)d_in[i]; break;
            case 18432:   weight = (const float*)d_in[i]; break;
            case 64:      bias   = (const float*)d_in[i]; break;
            case 2359296: smap   = (const float*)d_in[i]; break;
            default: break;
        }
    }
    float* out = (float*)d_out;

    static int n_sm = 0;
    if (n_sm == 0) {
        cudaFuncSetAttribute(mapped_conv_kernel,
                             cudaFuncAttributeMaxDynamicSharedMemorySize,
                             SMEM_BYTES);
        cudaDeviceGetAttribute(&n_sm, cudaDevAttrMultiProcessorCount, 0);
        if (n_sm <= 0) n_sm = 148;
    }

    // 1) transpose x -> g_xt
    {
        dim3 grid(HWSZ / 32, BB);
        dim3 block(32, 8);
        transpose_kernel<<<grid, block>>>(x);
    }

    // 2) gather + HMMA GEMM: persistent, 1 CTA/SM
    mapped_conv_kernel<<<n_sm, THREADS, SMEM_BYTES>>>(smap, weight, bias, out);
}